// round 12
// baseline (speedup 1.0000x reference)
#include <cuda_runtime.h>
#include <cuda_fp16.h>
#include <math.h>
#include <stdint.h>

// Problem dims (fixed): B=8, T=4096, D=H=1024
#define M_TOT   32768
#define N_TOT   1024
#define K_TOT   1024
#define T_LEN   4096
#define NCH     8192
#define NCHUNK  32
#define CHUNK   128           // == BM

// GEMM tiling: BK=64, 3 stages, half the barriers of round 11
#define BM      128
#define BN      64            // h-channels per CTA (x2 weight matrices)
#define BK      64
#define NKT     (K_TOT / BK)  // 16
#define AS      72            // smem row stride in halves (64+8, conflict-free LDSM)
#define A_HALFS (BM * AS)             // 9216
#define B_HALFS (2 * BN * AS)         // 9216
#define STAGE_H (A_HALFS + B_HALFS)   // 18432 halves = 36864 B
#define STAGES  3
#define SMEM_DYN (STAGES * STAGE_H * 2)   // 110592 B (>= 64KB pr + 2KB part + hin)

#define NTILES  16                         // n-tiles
#define NFLAGS  (256 * NTILES)             // (b,c) x nt = 4096

// Scratch (static device memory — no dynamic allocation allowed)
__device__ __half g_xh[(size_t)M_TOT * K_TOT];   // fp16 x, [m][k]
__device__ __half g_wh[2 * N_TOT * K_TOT];       // fp16 Wa||Wx transposed, [w][n][k]
__device__ float2 g_agg[NFLAGS * BN];            // per-(tile) chunk aggregate pairs
__device__ float  g_incl[NFLAGS * BN];           // per-(tile) inclusive h at chunk end
__device__ int    g_flag[NFLAGS];                // 0=none, 1=aggregate, 2=inclusive

// ---------------------------------------------------------------------------
// helpers
// ---------------------------------------------------------------------------
__device__ __forceinline__ uint32_t s2u(const void* p) {
    uint32_t a;
    asm("{ .reg .u64 t; cvta.to.shared.u64 t, %1; cvt.u32.u64 %0, t; }"
        : "=r"(a) : "l"(p));
    return a;
}
__device__ __forceinline__ void cp16(uint32_t dst, const void* src) {
    asm volatile("cp.async.ca.shared.global [%0], [%1], 16;" :: "r"(dst), "l"(src) : "memory");
}
__device__ __forceinline__ void cp_commit() {
    asm volatile("cp.async.commit_group;" ::: "memory");
}
__device__ __forceinline__ void cp_wait1() {
    asm volatile("cp.async.wait_group 1;" ::: "memory");
}
__device__ __forceinline__ void cp_wait0() {
    asm volatile("cp.async.wait_group 0;" ::: "memory");
}
#define LDSM4(r0, r1, r2, r3, addr) \
    asm volatile("ldmatrix.sync.aligned.m8n8.x4.shared.b16 {%0,%1,%2,%3}, [%4];" \
        : "=r"(r0), "=r"(r1), "=r"(r2), "=r"(r3) : "r"(addr))
__device__ __forceinline__ void mma_h(float* c, const uint32_t* a, const uint32_t* b) {
    asm volatile("mma.sync.aligned.m16n8k16.row.col.f32.f16.f16.f32 "
        "{%0,%1,%2,%3}, {%4,%5,%6,%7}, {%8,%9}, {%0,%1,%2,%3};"
        : "+f"(c[0]), "+f"(c[1]), "+f"(c[2]), "+f"(c[3])
        : "r"(a[0]), "r"(a[1]), "r"(a[2]), "r"(a[3]), "r"(b[0]), "r"(b[1]));
}
__device__ __forceinline__ float sigm(float v) {
    return __fdividef(1.0f, 1.0f + __expf(-v));
}

// ---------------------------------------------------------------------------
// Clear lookback flags (every launch)
// ---------------------------------------------------------------------------
__global__ void clear_flags_k()
{
    const int i = blockIdx.x * 256 + threadIdx.x;
    if (i < NFLAGS) g_flag[i] = 0;
}

// ---------------------------------------------------------------------------
// Pack x -> fp16 [m][k]
// ---------------------------------------------------------------------------
__global__ void pack_x_h(const float* __restrict__ x)
{
    const size_t i = ((size_t)blockIdx.x * 256 + threadIdx.x) * 8;
    const float4 v0 = *(const float4*)(x + i);
    const float4 v1 = *(const float4*)(x + i + 4);
    __half2 h[4];
    h[0] = __floats2half2_rn(v0.x, v0.y);
    h[1] = __floats2half2_rn(v0.z, v0.w);
    h[2] = __floats2half2_rn(v1.x, v1.y);
    h[3] = __floats2half2_rn(v1.z, v1.w);
    *(uint4*)(g_xh + i) = *(uint4*)h;
}

// ---------------------------------------------------------------------------
// Pack W -> fp16 transposed [w][n][k] (32x32 tiles via smem)
// ---------------------------------------------------------------------------
__global__ void pack_w_h(const float* __restrict__ Wa, const float* __restrict__ Wx)
{
    __shared__ float tile[32][33];
    const int bi = blockIdx.x;               // 0..2047
    const int w  = bi >> 10;
    const int kb = (bi >> 5) & 31;
    const int nb = bi & 31;
    const float* W = w ? Wx : Wa;
    const int k0 = kb * 32, n0 = nb * 32;
    const int tid = threadIdx.x;
    #pragma unroll
    for (int p = 0; p < 4; p++) {
        const int kk = (tid >> 5) + p * 8;
        const int n  = tid & 31;
        tile[kk][n] = W[(size_t)(k0 + kk) * N_TOT + n0 + n];
    }
    __syncthreads();
    #pragma unroll
    for (int p = 0; p < 4; p++) {
        const int n = (tid >> 5) + p * 8;
        const int k = tid & 31;
        g_wh[((size_t)w * N_TOT + n0 + n) * K_TOT + k0 + k] = __float2half_rn(tile[k][n]);
    }
}

// ---------------------------------------------------------------------------
// fp16 mma.sync dual-GEMM (ldmatrix, BK=64, 3-stage pipe, f32 accum)
// + fused gates + single-pass decoupled-lookback scan + direct y write.
// grid (16 n-tiles, 256 m-tiles), 256 threads (8 warps: 4M x 2N)
// ---------------------------------------------------------------------------
__global__ __launch_bounds__(256, 2)
void gemm_h(const float* __restrict__ x, const float* __restrict__ ba,
            const float* __restrict__ bx, const float* __restrict__ Lam,
            float* __restrict__ y)
{
    extern __shared__ __half smh[];
    __shared__ float a_s[BN], ba_s[BN], bx_s[BN];

    const int tid  = threadIdx.x;
    const int wid  = tid >> 5, lane = tid & 31;
    const int gid  = lane >> 2, tq = lane & 3;
    const int wm   = wid & 3, wn = wid >> 2;
    const int n0g  = blockIdx.x * BN;
    const int m0g  = blockIdx.y * BM;

    if (tid < BN) {
        const int n = n0g + tid;
        a_s[tid]  = sigm(Lam[n]);
        ba_s[tid] = ba[n];
        bx_s[tid] = bx[n];
    }

    // cp.async mapping (BK=64): A 128 rows x 8 slots of 8 halves = 1024 ops,
    // B same (128 rows = 2w x 64n). 4 ops each per thread.
    const int ar = tid >> 1;          // row 0..127
    const int ac = (tid & 1) * 4;     // slot base 0 or 4
    const uint32_t smb = s2u(smh);

    auto issue_stage = [&](int kt, int s) {
        const int k0 = kt * BK;
        const uint32_t st = smb + s * STAGE_H * 2;
        #pragma unroll
        for (int j = 0; j < 4; j++) {
            const int sl = ac + j;                         // slot 0..7
            cp16(st + (ar * AS + sl * 8) * 2,
                 g_xh + (size_t)(m0g + ar) * K_TOT + k0 + sl * 8);
        }
        const int w = ar >> 6, n = ar & 63;
        #pragma unroll
        for (int j = 0; j < 4; j++) {
            const int sl = ac + j;
            cp16(st + (A_HALFS + ar * AS + sl * 8) * 2,
                 g_wh + ((size_t)w * N_TOT + n0g + n) * K_TOT + k0 + sl * 8);
        }
    };

    const int m_base = wm * 32;
    const int n_base = wn * 32;

    // ldmatrix per-thread byte offsets (within a stage)
    uint32_t a_off[2];
    #pragma unroll
    for (int mi = 0; mi < 2; mi++)
        a_off[mi] = ((m_base + mi * 16 + (lane & 15)) * AS + (lane >> 4) * 8) * 2;
    uint32_t b_off[2][2];   // [set: 0=Wa,1=Wx][p]
    #pragma unroll
    for (int set = 0; set < 2; set++)
        #pragma unroll
        for (int p = 0; p < 2; p++)
            b_off[set][p] = (A_HALFS +
                (set * 64 + n_base + p * 16 + (lane & 7) + ((lane >> 4) & 1) * 8) * AS +
                ((lane >> 3) & 1) * 8) * 2;

    float accA[2][4][4], accX[2][4][4];
    #pragma unroll
    for (int mi = 0; mi < 2; mi++)
        #pragma unroll
        for (int ni = 0; ni < 4; ni++)
            #pragma unroll
            for (int j = 0; j < 4; j++) { accA[mi][ni][j] = 0.f; accX[mi][ni][j] = 0.f; }

    issue_stage(0, 0); cp_commit();
    issue_stage(1, 1); cp_commit();

    int sl_cur = 0;
    for (int kt = 0; kt < NKT; kt++) {
        cp_wait1();
        __syncthreads();
        // prefetch kt+2 into slot (sl_cur+2)%3 == slot of kt-1 (reads done pre-barrier)
        int sl_nxt = sl_cur + 2; if (sl_nxt >= 3) sl_nxt -= 3;
        if (kt + 2 < NKT) issue_stage(kt + 2, sl_nxt);
        cp_commit();

        const uint32_t stb = smb + sl_cur * STAGE_H * 2;
        #pragma unroll
        for (int s = 0; s < 4; s++) {
            const uint32_t ksb = stb + s * 32;     // s*16 halves
            uint32_t af[2][4];
            #pragma unroll
            for (int mi = 0; mi < 2; mi++)
                LDSM4(af[mi][0], af[mi][1], af[mi][2], af[mi][3], ksb + a_off[mi]);
            uint32_t bfa[4][2], bfx[4][2];
            #pragma unroll
            for (int p = 0; p < 2; p++) {
                LDSM4(bfa[2*p][0], bfa[2*p][1], bfa[2*p+1][0], bfa[2*p+1][1], ksb + b_off[0][p]);
                LDSM4(bfx[2*p][0], bfx[2*p][1], bfx[2*p+1][0], bfx[2*p+1][1], ksb + b_off[1][p]);
            }
            #pragma unroll
            for (int mi = 0; mi < 2; mi++)
                #pragma unroll
                for (int ni = 0; ni < 4; ni++) {
                    mma_h(accA[mi][ni], af[mi], bfa[ni]);
                    mma_h(accX[mi][ni], af[mi], bfx[ni]);
                }
        }
        sl_cur = sl_cur + 1 == 3 ? 0 : sl_cur + 1;
    }

    // --- Epilogue: gate math -> smem (at,bt) staging ---
    cp_wait0();
    __syncthreads();                       // pipeline smem now dead; reuse below
    float2* pr   = (float2*)smh;                 // [128 rows][64 ch], 64 KB
    float2* part = (float2*)(smh + 65536 / 2);   // [4 seg][64 ch], 2 KB
    float*  hin_s = (float*)(part + 256);        // [64 ch], 256 B

    #pragma unroll
    for (int mi = 0; mi < 2; mi++) {
        #pragma unroll
        for (int half = 0; half < 2; half++) {
            const int rloc = m_base + mi * 16 + gid + half * 8;     // 0..127
            const int row  = m0g + rloc;
            const float* xr = x + (size_t)row * N_TOT;
            #pragma unroll
            for (int ni = 0; ni < 4; ni++) {
                const int nl = n_base + ni * 8 + tq * 2;
                const int n  = n0g + nl;
                const float vA0 = accA[mi][ni][half * 2];
                const float vA1 = accA[mi][ni][half * 2 + 1];
                const float vX0 = accX[mi][ni][half * 2];
                const float vX1 = accX[mi][ni][half * 2 + 1];
                const float2 xv = *(const float2*)(xr + n);
                const float r0 = sigm(vA0 + ba_s[nl]);
                const float r1 = sigm(vA1 + ba_s[nl + 1]);
                const float i0 = sigm(vX0 + bx_s[nl]);
                const float i1 = sigm(vX1 + bx_s[nl + 1]);
                const float at0 = a_s[nl]     * exp2f(-3.0f * r0);
                const float at1 = a_s[nl + 1] * exp2f(-3.0f * r1);
                const float bt0 = sqrtf(fmaxf(1.0f - at0 * at0, 0.0f)) * (i0 * xv.x);
                const float bt1 = sqrtf(fmaxf(1.0f - at1 * at1, 0.0f)) * (i1 * xv.y);
                pr[rloc * BN + nl]     = make_float2(at0, bt0);
                pr[rloc * BN + nl + 1] = make_float2(at1, bt1);
            }
        }
    }
    __syncthreads();

    // --- Chunk-pair reduction: 4 segments of 32 rows per channel ---
    {
        const int ch  = tid & 63;
        const int seg = tid >> 6;
        float A = 1.0f, Bv = 0.0f;
        #pragma unroll 8
        for (int r = 0; r < 32; r++) {
            const float2 v = pr[(seg * 32 + r) * BN + ch];
            Bv = fmaf(v.x, Bv, v.y);
            A *= v.x;
        }
        part[seg * 64 + ch] = make_float2(A, Bv);
    }
    __syncthreads();

    // --- Decoupled lookback across chunks (per n-tile, per batch) ---
    const int c  = (m0g >> 7) & 31;                 // chunk within batch
    const int fi = blockIdx.y * NTILES + blockIdx.x;
    volatile int* vflag = g_flag;

    float2 P;
    if (tid < 64) {
        P = part[tid];
        #pragma unroll
        for (int s = 1; s < 4; s++) {
            const float2 q = part[s * 64 + tid];
            P.y = fmaf(q.x, P.y, q.y);
            P.x *= q.x;
        }
        if (c > 0) g_agg[fi * 64 + tid] = P;        // publish aggregate payload
    }
    __syncthreads();
    if (tid == 0 && c > 0) {
        __threadfence();
        vflag[fi] = 1;
    }

    if (tid < 64) {
        float hin = 0.0f;
        if (c > 0) {
            float rA = 1.0f, rB = 0.0f;             // pending suffix combine
            int p = fi - NTILES;                    // predecessor chunk, same nt
            while (true) {
                int f;
                while ((f = vflag[p]) == 0) { __nanosleep(40); }
                __threadfence();
                if (f == 2) {
                    const float hprev = g_incl[p * 64 + tid];
                    hin = fmaf(rA, hprev, rB);
                    break;
                } else {
                    const float2 q = g_agg[p * 64 + tid];
                    rB = fmaf(rA, q.y, rB);
                    rA *= q.x;
                    p -= NTILES;
                }
            }
        }
        g_incl[fi * 64 + tid] = fmaf(P.x, hin, P.y);   // inclusive h at chunk end
        hin_s[tid] = hin;
    }
    __syncthreads();
    if (tid == 0) {
        __threadfence();
        vflag[fi] = 2;
    }

    // --- Serial scan of 32 rows per (segment, channel); direct y write ---
    {
        const int ch  = tid & 63;
        const int seg = tid >> 6;
        float h = hin_s[ch];
        #pragma unroll
        for (int s = 0; s < 4; s++)
            if (s < seg) {
                const float2 q = part[s * 64 + ch];
                h = fmaf(q.x, h, q.y);
            }
        float* yr = y + (size_t)(m0g + seg * 32) * N_TOT + n0g + ch;
        #pragma unroll 8
        for (int r = 0; r < 32; r++) {
            const float2 v = pr[(seg * 32 + r) * BN + ch];
            h = fmaf(v.x, h, v.y);
            yr[(size_t)r * N_TOT] = h;
        }
    }
}

// ---------------------------------------------------------------------------
// Launch: inputs x, Wa, Wx, ba, bx, Lam. Output f32 [B,T,H].
// ---------------------------------------------------------------------------
extern "C" void kernel_launch(void* const* d_in, const int* in_sizes, int n_in,
                              void* d_out, int out_size)
{
    const float* x   = (const float*)d_in[0];
    const float* Wa  = (const float*)d_in[1];
    const float* Wx  = (const float*)d_in[2];
    const float* ba  = (const float*)d_in[3];
    const float* bx  = (const float*)d_in[4];
    const float* Lam = (const float*)d_in[5];
    float* y = (float*)d_out;

    cudaFuncSetAttribute(gemm_h, cudaFuncAttributeMaxDynamicSharedMemorySize, SMEM_DYN);

    clear_flags_k<<<(NFLAGS + 255) / 256, 256>>>();
    pack_x_h<<<M_TOT * K_TOT / 2048, 256>>>(x);
    pack_w_h<<<2048, 256>>>(Wa, Wx);
    gemm_h<<<dim3(N_TOT / BN, M_TOT / BM), 256, SMEM_DYN>>>(x, ba, bx, Lam, y);
}

// round 13
// speedup vs baseline: 1.2445x; 1.2445x over previous
#include <cuda_runtime.h>
#include <cuda_fp16.h>
#include <math.h>
#include <stdint.h>

// Problem dims (fixed): B=8, T=4096, D=H=1024
#define M_TOT   32768
#define N_TOT   1024
#define K_TOT   1024
#define T_LEN   4096
#define NCH     8192
#define NCHUNK  32
#define CHUNK   128           // == BM

// GEMM tiling (round-11 proven config)
#define BM      128
#define BN      64            // h-channels per CTA (x2 weight matrices)
#define BK      32
#define NKT     (K_TOT / BK)  // 32
#define AS      40            // smem row stride in halves (conflict-free)
#define A_HALFS (BM * AS)             // 5120
#define B_HALFS (2 * BN * AS)         // 5120
#define STAGE_H (A_HALFS + B_HALFS)   // 10240 halves = 20480 B
#define STAGES  4
#define SMEM_DYN (STAGES * STAGE_H * 2)   // 81920 B (>= 64KB pr + 2KB part + hin)

#define NTILES  16                         // n-tiles
#define NFLAGS  (256 * NTILES)             // (b,c) x nt = 4096

// Scratch (static device memory — no dynamic allocation allowed)
__device__ __half g_xh[(size_t)M_TOT * K_TOT];   // fp16 x, [m][k]
__device__ __half g_wh[2 * N_TOT * K_TOT];       // fp16 Wa||Wx transposed, [w][n][k]
__device__ float2 g_agg[NFLAGS * BN];            // per-(tile) chunk aggregate pairs
__device__ float  g_incl[NFLAGS * BN];           // per-(tile) inclusive h at chunk end
__device__ int    g_flag[NFLAGS];                // 0=none, 1=aggregate, 2=inclusive

// ---------------------------------------------------------------------------
// helpers
// ---------------------------------------------------------------------------
__device__ __forceinline__ uint32_t s2u(const void* p) {
    uint32_t a;
    asm("{ .reg .u64 t; cvta.to.shared.u64 t, %1; cvt.u32.u64 %0, t; }"
        : "=r"(a) : "l"(p));
    return a;
}
__device__ __forceinline__ void cp16(uint32_t dst, const void* src) {
    asm volatile("cp.async.ca.shared.global [%0], [%1], 16;" :: "r"(dst), "l"(src) : "memory");
}
__device__ __forceinline__ void cp_commit() {
    asm volatile("cp.async.commit_group;" ::: "memory");
}
__device__ __forceinline__ void cp_wait2() {
    asm volatile("cp.async.wait_group 2;" ::: "memory");
}
__device__ __forceinline__ void cp_wait0() {
    asm volatile("cp.async.wait_group 0;" ::: "memory");
}
#define LDSM4(r0, r1, r2, r3, addr) \
    asm volatile("ldmatrix.sync.aligned.m8n8.x4.shared.b16 {%0,%1,%2,%3}, [%4];" \
        : "=r"(r0), "=r"(r1), "=r"(r2), "=r"(r3) : "r"(addr))
__device__ __forceinline__ void mma_h(float* c, const uint32_t* a, const uint32_t* b) {
    asm volatile("mma.sync.aligned.m16n8k16.row.col.f32.f16.f16.f32 "
        "{%0,%1,%2,%3}, {%4,%5,%6,%7}, {%8,%9}, {%0,%1,%2,%3};"
        : "+f"(c[0]), "+f"(c[1]), "+f"(c[2]), "+f"(c[3])
        : "r"(a[0]), "r"(a[1]), "r"(a[2]), "r"(a[3]), "r"(b[0]), "r"(b[1]));
}
__device__ __forceinline__ float sigm(float v) {
    return __fdividef(1.0f, 1.0f + __expf(-v));
}

// ---------------------------------------------------------------------------
// Pack x -> fp16 [m][k]; blocks 0..NFLAGS/256-1 also clear lookback flags
// ---------------------------------------------------------------------------
__global__ void pack_x_h(const float* __restrict__ x)
{
    if (blockIdx.x < NFLAGS / 256)
        g_flag[blockIdx.x * 256 + threadIdx.x] = 0;
    const size_t i = ((size_t)blockIdx.x * 256 + threadIdx.x) * 8;
    const float4 v0 = *(const float4*)(x + i);
    const float4 v1 = *(const float4*)(x + i + 4);
    __half2 h[4];
    h[0] = __floats2half2_rn(v0.x, v0.y);
    h[1] = __floats2half2_rn(v0.z, v0.w);
    h[2] = __floats2half2_rn(v1.x, v1.y);
    h[3] = __floats2half2_rn(v1.z, v1.w);
    *(uint4*)(g_xh + i) = *(uint4*)h;
}

// ---------------------------------------------------------------------------
// Pack W -> fp16 transposed [w][n][k] (32x32 tiles via smem)
// ---------------------------------------------------------------------------
__global__ void pack_w_h(const float* __restrict__ Wa, const float* __restrict__ Wx)
{
    __shared__ float tile[32][33];
    const int bi = blockIdx.x;               // 0..2047
    const int w  = bi >> 10;
    const int kb = (bi >> 5) & 31;
    const int nb = bi & 31;
    const float* W = w ? Wx : Wa;
    const int k0 = kb * 32, n0 = nb * 32;
    const int tid = threadIdx.x;
    #pragma unroll
    for (int p = 0; p < 4; p++) {
        const int kk = (tid >> 5) + p * 8;
        const int n  = tid & 31;
        tile[kk][n] = W[(size_t)(k0 + kk) * N_TOT + n0 + n];
    }
    __syncthreads();
    #pragma unroll
    for (int p = 0; p < 4; p++) {
        const int n = (tid >> 5) + p * 8;
        const int k = tid & 31;
        g_wh[((size_t)w * N_TOT + n0 + n) * K_TOT + k0 + k] = __float2half_rn(tile[k][n]);
    }
}

// ---------------------------------------------------------------------------
// fp16 mma.sync dual-GEMM (ldmatrix + 4-stage pipe, f32 accum) + fused gates
// + single-pass decoupled-lookback scan + direct y write.
// grid (16 n-tiles, 256 m-tiles), 256 threads (8 warps: 4M x 2N)
// ---------------------------------------------------------------------------
__global__ __launch_bounds__(256, 2)
void gemm_h(const float* __restrict__ x, const float* __restrict__ ba,
            const float* __restrict__ bx, const float* __restrict__ Lam,
            float* __restrict__ y)
{
    extern __shared__ __half smh[];
    __shared__ float a_s[BN], ba_s[BN], bx_s[BN];

    const int tid  = threadIdx.x;
    const int wid  = tid >> 5, lane = tid & 31;
    const int gid  = lane >> 2, tq = lane & 3;
    const int wm   = wid & 3, wn = wid >> 2;
    const int n0g  = blockIdx.x * BN;
    const int m0g  = blockIdx.y * BM;

    if (tid < BN) {
        const int n = n0g + tid;
        a_s[tid]  = sigm(Lam[n]);
        ba_s[tid] = ba[n];
        bx_s[tid] = bx[n];
    }

    // cp.async mapping: 128 rows x 4 slots of 8 halves, for A and for B
    const int ar = tid >> 2;     // 0..63
    const int ac = tid & 3;      // slot 0..3
    const uint32_t smb = s2u(smh);

    auto issue_stage = [&](int kt, int s) {
        const int k0 = kt * BK;
        const uint32_t st = smb + s * STAGE_H * 2;
        #pragma unroll
        for (int r = 0; r < 2; r++) {
            const int row = ar + r * 64;                   // 0..127
            cp16(st + (row * AS + ac * 8) * 2,
                 g_xh + (size_t)(m0g + row) * K_TOT + k0 + ac * 8);
        }
        #pragma unroll
        for (int r = 0; r < 2; r++) {
            const int row = ar + r * 64;                   // 0..127: w=row>>6, n=row&63
            const int w = row >> 6, n = row & 63;
            cp16(st + (A_HALFS + row * AS + ac * 8) * 2,
                 g_wh + ((size_t)w * N_TOT + n0g + n) * K_TOT + k0 + ac * 8);
        }
    };

    const int m_base = wm * 32;
    const int n_base = wn * 32;

    // ldmatrix per-thread byte offsets (within a stage)
    uint32_t a_off[2];
    #pragma unroll
    for (int mi = 0; mi < 2; mi++)
        a_off[mi] = ((m_base + mi * 16 + (lane & 15)) * AS + (lane >> 4) * 8) * 2;
    uint32_t b_off[2][2];   // [set: 0=Wa,1=Wx][p]
    #pragma unroll
    for (int set = 0; set < 2; set++)
        #pragma unroll
        for (int p = 0; p < 2; p++)
            b_off[set][p] = (A_HALFS +
                (set * 64 + n_base + p * 16 + (lane & 7) + ((lane >> 4) & 1) * 8) * AS +
                ((lane >> 3) & 1) * 8) * 2;

    float accA[2][4][4], accX[2][4][4];
    #pragma unroll
    for (int mi = 0; mi < 2; mi++)
        #pragma unroll
        for (int ni = 0; ni < 4; ni++)
            #pragma unroll
            for (int j = 0; j < 4; j++) { accA[mi][ni][j] = 0.f; accX[mi][ni][j] = 0.f; }

    issue_stage(0, 0); cp_commit();
    issue_stage(1, 1); cp_commit();
    issue_stage(2, 2); cp_commit();

    for (int kt = 0; kt < NKT; kt++) {
        cp_wait2();
        __syncthreads();
        // Early prefetch: slot (kt+3)&3 == (kt-1)&3; all reads of it finished
        // before every warp passed this iteration's barrier.
        if (kt + 3 < NKT) issue_stage(kt + 3, (kt + 3) & 3);
        cp_commit();

        const uint32_t stb = smb + (kt & 3) * STAGE_H * 2;
        #pragma unroll
        for (int s = 0; s < 2; s++) {
            const uint32_t ksb = stb + s * 32;
            uint32_t af[2][4];
            #pragma unroll
            for (int mi = 0; mi < 2; mi++)
                LDSM4(af[mi][0], af[mi][1], af[mi][2], af[mi][3], ksb + a_off[mi]);
            uint32_t bfa[4][2], bfx[4][2];
            #pragma unroll
            for (int p = 0; p < 2; p++) {
                LDSM4(bfa[2*p][0], bfa[2*p][1], bfa[2*p+1][0], bfa[2*p+1][1], ksb + b_off[0][p]);
                LDSM4(bfx[2*p][0], bfx[2*p][1], bfx[2*p+1][0], bfx[2*p+1][1], ksb + b_off[1][p]);
            }
            #pragma unroll
            for (int mi = 0; mi < 2; mi++)
                #pragma unroll
                for (int ni = 0; ni < 4; ni++) {
                    mma_h(accA[mi][ni], af[mi], bfa[ni]);
                    mma_h(accX[mi][ni], af[mi], bfx[ni]);
                }
        }
    }

    // --- Epilogue: gate math -> smem (at,bt) staging ---
    cp_wait0();
    __syncthreads();                       // pipeline smem now dead; reuse below
    float2* pr   = (float2*)smh;                 // [128 rows][64 ch], 64 KB
    float2* part = (float2*)(smh + 65536 / 2);   // [4 seg][64 ch], 2 KB
    float*  hin_s = (float*)(part + 256);        // [64 ch], 256 B

    #pragma unroll
    for (int mi = 0; mi < 2; mi++) {
        #pragma unroll
        for (int half = 0; half < 2; half++) {
            const int rloc = m_base + mi * 16 + gid + half * 8;     // 0..127
            const int row  = m0g + rloc;
            const float* xr = x + (size_t)row * N_TOT;
            #pragma unroll
            for (int ni = 0; ni < 4; ni++) {
                const int nl = n_base + ni * 8 + tq * 2;
                const int n  = n0g + nl;
                const float vA0 = accA[mi][ni][half * 2];
                const float vA1 = accA[mi][ni][half * 2 + 1];
                const float vX0 = accX[mi][ni][half * 2];
                const float vX1 = accX[mi][ni][half * 2 + 1];
                const float2 xv = *(const float2*)(xr + n);
                const float r0 = sigm(vA0 + ba_s[nl]);
                const float r1 = sigm(vA1 + ba_s[nl + 1]);
                const float i0 = sigm(vX0 + bx_s[nl]);
                const float i1 = sigm(vX1 + bx_s[nl + 1]);
                const float at0 = a_s[nl]     * exp2f(-3.0f * r0);
                const float at1 = a_s[nl + 1] * exp2f(-3.0f * r1);
                const float bt0 = sqrtf(fmaxf(1.0f - at0 * at0, 0.0f)) * (i0 * xv.x);
                const float bt1 = sqrtf(fmaxf(1.0f - at1 * at1, 0.0f)) * (i1 * xv.y);
                pr[rloc * BN + nl]     = make_float2(at0, bt0);
                pr[rloc * BN + nl + 1] = make_float2(at1, bt1);
            }
        }
    }
    __syncthreads();

    // --- Chunk-pair reduction: 4 segments of 32 rows per channel ---
    {
        const int ch  = tid & 63;
        const int seg = tid >> 6;
        float A = 1.0f, Bv = 0.0f;
        #pragma unroll 8
        for (int r = 0; r < 32; r++) {
            const float2 v = pr[(seg * 32 + r) * BN + ch];
            Bv = fmaf(v.x, Bv, v.y);
            A *= v.x;
        }
        part[seg * 64 + ch] = make_float2(A, Bv);
    }
    __syncthreads();

    // --- Decoupled lookback across chunks (per n-tile, per batch) ---
    const int c  = (m0g >> 7) & 31;                 // chunk within batch
    const int fi = blockIdx.y * NTILES + blockIdx.x;
    volatile int* vflag = g_flag;

    float2 P;
    if (tid < 64) {
        P = part[tid];
        #pragma unroll
        for (int s = 1; s < 4; s++) {
            const float2 q = part[s * 64 + tid];
            P.y = fmaf(q.x, P.y, q.y);
            P.x *= q.x;
        }
        if (c > 0) g_agg[fi * 64 + tid] = P;        // publish aggregate payload
    }
    __syncthreads();
    if (tid == 0 && c > 0) {
        __threadfence();
        vflag[fi] = 1;
    }

    if (tid < 64) {
        float hin = 0.0f;
        if (c > 0) {
            float rA = 1.0f, rB = 0.0f;             // pending suffix combine
            int p = fi - NTILES;                    // predecessor chunk, same nt
            while (true) {
                int f;
                while ((f = vflag[p]) == 0) { __nanosleep(40); }
                __threadfence();
                if (f == 2) {
                    const float hprev = g_incl[p * 64 + tid];
                    hin = fmaf(rA, hprev, rB);
                    break;
                } else {
                    const float2 q = g_agg[p * 64 + tid];
                    rB = fmaf(rA, q.y, rB);
                    rA *= q.x;
                    p -= NTILES;
                }
            }
        }
        g_incl[fi * 64 + tid] = fmaf(P.x, hin, P.y);   // inclusive h at chunk end
        hin_s[tid] = hin;
    }
    __syncthreads();
    if (tid == 0) {
        __threadfence();
        vflag[fi] = 2;
    }

    // --- Serial scan of 32 rows per (segment, channel); direct y write ---
    {
        const int ch  = tid & 63;
        const int seg = tid >> 6;
        float h = hin_s[ch];
        #pragma unroll
        for (int s = 0; s < 4; s++)
            if (s < seg) {
                const float2 q = part[s * 64 + ch];
                h = fmaf(q.x, h, q.y);
            }
        float* yr = y + (size_t)(m0g + seg * 32) * N_TOT + n0g + ch;
        #pragma unroll 8
        for (int r = 0; r < 32; r++) {
            const float2 v = pr[(seg * 32 + r) * BN + ch];
            h = fmaf(v.x, h, v.y);
            yr[(size_t)r * N_TOT] = h;
        }
    }
}

// ---------------------------------------------------------------------------
// Launch: inputs x, Wa, Wx, ba, bx, Lam. Output f32 [B,T,H].
// ---------------------------------------------------------------------------
extern "C" void kernel_launch(void* const* d_in, const int* in_sizes, int n_in,
                              void* d_out, int out_size)
{
    const float* x   = (const float*)d_in[0];
    const float* Wa  = (const float*)d_in[1];
    const float* Wx  = (const float*)d_in[2];
    const float* ba  = (const float*)d_in[3];
    const float* bx  = (const float*)d_in[4];
    const float* Lam = (const float*)d_in[5];
    float* y = (float*)d_out;

    cudaFuncSetAttribute(gemm_h, cudaFuncAttributeMaxDynamicSharedMemorySize, SMEM_DYN);

    pack_x_h<<<M_TOT * K_TOT / 2048, 256>>>(x);
    pack_w_h<<<2048, 256>>>(Wa, Wx);
    gemm_h<<<dim3(N_TOT / BN, M_TOT / BM), 256, SMEM_DYN>>>(x, ba, bx, Lam, y);
}

// round 14
// speedup vs baseline: 1.3451x; 1.0809x over previous
#include <cuda_runtime.h>
#include <cuda_fp16.h>
#include <math.h>
#include <stdint.h>

// Problem dims (fixed): B=8, T=4096, D=H=1024
#define M_TOT   32768
#define N_TOT   1024
#define K_TOT   1024
#define T_LEN   4096
#define NCH     8192
#define NCHUNK  32
#define CHUNK   128           // == BM

// GEMM tiling (round-11 proven config)
#define BM      128
#define BN      64            // h-channels per CTA (x2 weight matrices)
#define BK      32
#define NKT     (K_TOT / BK)  // 32
#define AS      40            // smem row stride in halves (conflict-free)
#define A_HALFS (BM * AS)             // 5120
#define B_HALFS (2 * BN * AS)         // 5120
#define STAGE_H (A_HALFS + B_HALFS)   // 10240 halves = 20480 B
#define STAGES  4
#define SMEM_DYN (STAGES * STAGE_H * 2)   // 81920 B (>= 64KB pr + 2KB part + hin)

#define NTILES  16                         // n-tiles
#define NFLAGS  (256 * NTILES)             // (b,c) x nt = 4096

// Scratch (static device memory — no dynamic allocation allowed)
__device__ __half g_xh[(size_t)M_TOT * K_TOT];   // fp16 x, [m][k]
__device__ __half g_wh[2 * N_TOT * K_TOT];       // fp16 Wa||Wx transposed, [w][n][k]
__device__ float2 g_agg[NFLAGS * BN];            // per-(tile) chunk aggregate pairs
__device__ float  g_incl[NFLAGS * BN];           // per-(tile) inclusive h at chunk end
__device__ int    g_flag[NFLAGS];                // 0=none, 1=aggregate, 2=inclusive

// ---------------------------------------------------------------------------
// helpers
// ---------------------------------------------------------------------------
__device__ __forceinline__ uint32_t s2u(const void* p) {
    uint32_t a;
    asm("{ .reg .u64 t; cvta.to.shared.u64 t, %1; cvt.u32.u64 %0, t; }"
        : "=r"(a) : "l"(p));
    return a;
}
__device__ __forceinline__ void cp16(uint32_t dst, const void* src) {
    asm volatile("cp.async.ca.shared.global [%0], [%1], 16;" :: "r"(dst), "l"(src) : "memory");
}
__device__ __forceinline__ void cp_commit() {
    asm volatile("cp.async.commit_group;" ::: "memory");
}
__device__ __forceinline__ void cp_wait2() {
    asm volatile("cp.async.wait_group 2;" ::: "memory");
}
__device__ __forceinline__ void cp_wait0() {
    asm volatile("cp.async.wait_group 0;" ::: "memory");
}
#define LDSM4(r0, r1, r2, r3, addr) \
    asm volatile("ldmatrix.sync.aligned.m8n8.x4.shared.b16 {%0,%1,%2,%3}, [%4];" \
        : "=r"(r0), "=r"(r1), "=r"(r2), "=r"(r3) : "r"(addr))
__device__ __forceinline__ void mma_h(float* c, const uint32_t* a, const uint32_t* b) {
    asm volatile("mma.sync.aligned.m16n8k16.row.col.f32.f16.f16.f32 "
        "{%0,%1,%2,%3}, {%4,%5,%6,%7}, {%8,%9}, {%0,%1,%2,%3};"
        : "+f"(c[0]), "+f"(c[1]), "+f"(c[2]), "+f"(c[3])
        : "r"(a[0]), "r"(a[1]), "r"(a[2]), "r"(a[3]), "r"(b[0]), "r"(b[1]));
}
__device__ __forceinline__ float sigm(float v) {
    return __fdividef(1.0f, 1.0f + __expf(-v));
}

// ---------------------------------------------------------------------------
// Pack x -> fp16 [m][k]; blocks 0..NFLAGS/256-1 also clear lookback flags
// ---------------------------------------------------------------------------
__global__ void pack_x_h(const float* __restrict__ x)
{
    if (blockIdx.x < NFLAGS / 256)
        g_flag[blockIdx.x * 256 + threadIdx.x] = 0;
    const size_t i = ((size_t)blockIdx.x * 256 + threadIdx.x) * 8;
    const float4 v0 = *(const float4*)(x + i);
    const float4 v1 = *(const float4*)(x + i + 4);
    __half2 h[4];
    h[0] = __floats2half2_rn(v0.x, v0.y);
    h[1] = __floats2half2_rn(v0.z, v0.w);
    h[2] = __floats2half2_rn(v1.x, v1.y);
    h[3] = __floats2half2_rn(v1.z, v1.w);
    *(uint4*)(g_xh + i) = *(uint4*)h;
}

// ---------------------------------------------------------------------------
// Pack W -> fp16 transposed [w][n][k] (32x32 tiles via smem)
// ---------------------------------------------------------------------------
__global__ void pack_w_h(const float* __restrict__ Wa, const float* __restrict__ Wx)
{
    __shared__ float tile[32][33];
    const int bi = blockIdx.x;               // 0..2047
    const int w  = bi >> 10;
    const int kb = (bi >> 5) & 31;
    const int nb = bi & 31;
    const float* W = w ? Wx : Wa;
    const int k0 = kb * 32, n0 = nb * 32;
    const int tid = threadIdx.x;
    #pragma unroll
    for (int p = 0; p < 4; p++) {
        const int kk = (tid >> 5) + p * 8;
        const int n  = tid & 31;
        tile[kk][n] = W[(size_t)(k0 + kk) * N_TOT + n0 + n];
    }
    __syncthreads();
    #pragma unroll
    for (int p = 0; p < 4; p++) {
        const int n = (tid >> 5) + p * 8;
        const int k = tid & 31;
        g_wh[((size_t)w * N_TOT + n0 + n) * K_TOT + k0 + k] = __float2half_rn(tile[k][n]);
    }
}

// ---------------------------------------------------------------------------
// fp16 mma.sync dual-GEMM (ldmatrix + 4-stage pipe, f32 accum) + fused gates
// + single-pass decoupled-lookback scan + direct y write.
// grid (16 n-tiles, 256 m-tiles), 256 threads (8 warps: 4M x 2N)
// ---------------------------------------------------------------------------
__global__ __launch_bounds__(256, 2)
void gemm_h(const float* __restrict__ x, const float* __restrict__ ba,
            const float* __restrict__ bx, const float* __restrict__ Lam,
            float* __restrict__ y)
{
    extern __shared__ __half smh[];
    __shared__ float a_s[BN], ba_s[BN], bx_s[BN];

    const int tid  = threadIdx.x;
    const int wid  = tid >> 5, lane = tid & 31;
    const int gid  = lane >> 2, tq = lane & 3;
    const int wm   = wid & 3, wn = wid >> 2;
    const int n0g  = blockIdx.x * BN;
    const int m0g  = blockIdx.y * BM;

    if (tid < BN) {
        const int n = n0g + tid;
        a_s[tid]  = sigm(Lam[n]);
        ba_s[tid] = ba[n];
        bx_s[tid] = bx[n];
    }

    // cp.async mapping: 128 rows x 4 slots of 8 halves, for A and for B
    const int ar = tid >> 2;     // 0..63
    const int ac = tid & 3;      // slot 0..3
    const uint32_t smb = s2u(smh);

    auto issue_stage = [&](int kt, int s) {
        const int k0 = kt * BK;
        const uint32_t st = smb + s * STAGE_H * 2;
        #pragma unroll
        for (int r = 0; r < 2; r++) {
            const int row = ar + r * 64;                   // 0..127
            cp16(st + (row * AS + ac * 8) * 2,
                 g_xh + (size_t)(m0g + row) * K_TOT + k0 + ac * 8);
        }
        #pragma unroll
        for (int r = 0; r < 2; r++) {
            const int row = ar + r * 64;                   // 0..127: w=row>>6, n=row&63
            const int w = row >> 6, n = row & 63;
            cp16(st + (A_HALFS + row * AS + ac * 8) * 2,
                 g_wh + ((size_t)w * N_TOT + n0g + n) * K_TOT + k0 + ac * 8);
        }
    };

    const int m_base = wm * 32;
    const int n_base = wn * 32;

    // ldmatrix per-thread byte offsets (within a stage)
    uint32_t a_off[2];
    #pragma unroll
    for (int mi = 0; mi < 2; mi++)
        a_off[mi] = ((m_base + mi * 16 + (lane & 15)) * AS + (lane >> 4) * 8) * 2;
    uint32_t b_off[2][2];   // [set: 0=Wa,1=Wx][p]
    #pragma unroll
    for (int set = 0; set < 2; set++)
        #pragma unroll
        for (int p = 0; p < 2; p++)
            b_off[set][p] = (A_HALFS +
                (set * 64 + n_base + p * 16 + (lane & 7) + ((lane >> 4) & 1) * 8) * AS +
                ((lane >> 3) & 1) * 8) * 2;

    float accA[2][4][4], accX[2][4][4];
    #pragma unroll
    for (int mi = 0; mi < 2; mi++)
        #pragma unroll
        for (int ni = 0; ni < 4; ni++)
            #pragma unroll
            for (int j = 0; j < 4; j++) { accA[mi][ni][j] = 0.f; accX[mi][ni][j] = 0.f; }

    issue_stage(0, 0); cp_commit();
    issue_stage(1, 1); cp_commit();
    issue_stage(2, 2); cp_commit();

    for (int kt = 0; kt < NKT; kt++) {
        cp_wait2();
        __syncthreads();
        const uint32_t stb = smb + (kt & 3) * STAGE_H * 2;

        #pragma unroll
        for (int s = 0; s < 2; s++) {
            const uint32_t ksb = stb + s * 32;
            uint32_t af[2][4];
            #pragma unroll
            for (int mi = 0; mi < 2; mi++)
                LDSM4(af[mi][0], af[mi][1], af[mi][2], af[mi][3], ksb + a_off[mi]);
            uint32_t bfa[4][2], bfx[4][2];
            #pragma unroll
            for (int p = 0; p < 2; p++) {
                LDSM4(bfa[2*p][0], bfa[2*p][1], bfa[2*p+1][0], bfa[2*p+1][1], ksb + b_off[0][p]);
                LDSM4(bfx[2*p][0], bfx[2*p][1], bfx[2*p+1][0], bfx[2*p+1][1], ksb + b_off[1][p]);
            }
            #pragma unroll
            for (int mi = 0; mi < 2; mi++)
                #pragma unroll
                for (int ni = 0; ni < 4; ni++) {
                    mma_h(accA[mi][ni], af[mi], bfa[ni]);
                    mma_h(accX[mi][ni], af[mi], bfx[ni]);
                }
        }
        // Prefetch AFTER the MMA block (round-11 measured optimum): slot
        // (kt+3)&3 == (kt-1)&3; all warps finished reading it pre-barrier.
        if (kt + 3 < NKT) issue_stage(kt + 3, (kt + 3) & 3);
        cp_commit();
    }

    // --- Epilogue: gate math -> smem (at,bt) staging ---
    cp_wait0();
    __syncthreads();                       // pipeline smem now dead; reuse below
    float2* pr   = (float2*)smh;                 // [128 rows][64 ch], 64 KB
    float2* part = (float2*)(smh + 65536 / 2);   // [4 seg][64 ch], 2 KB
    float*  hin_s = (float*)(part + 256);        // [64 ch], 256 B

    #pragma unroll
    for (int mi = 0; mi < 2; mi++) {
        #pragma unroll
        for (int half = 0; half < 2; half++) {
            const int rloc = m_base + mi * 16 + gid + half * 8;     // 0..127
            const int row  = m0g + rloc;
            const float* xr = x + (size_t)row * N_TOT;
            #pragma unroll
            for (int ni = 0; ni < 4; ni++) {
                const int nl = n_base + ni * 8 + tq * 2;
                const int n  = n0g + nl;
                const float vA0 = accA[mi][ni][half * 2];
                const float vA1 = accA[mi][ni][half * 2 + 1];
                const float vX0 = accX[mi][ni][half * 2];
                const float vX1 = accX[mi][ni][half * 2 + 1];
                const float2 xv = *(const float2*)(xr + n);
                const float r0 = sigm(vA0 + ba_s[nl]);
                const float r1 = sigm(vA1 + ba_s[nl + 1]);
                const float i0 = sigm(vX0 + bx_s[nl]);
                const float i1 = sigm(vX1 + bx_s[nl + 1]);
                const float at0 = a_s[nl]     * exp2f(-3.0f * r0);
                const float at1 = a_s[nl + 1] * exp2f(-3.0f * r1);
                const float bt0 = sqrtf(fmaxf(1.0f - at0 * at0, 0.0f)) * (i0 * xv.x);
                const float bt1 = sqrtf(fmaxf(1.0f - at1 * at1, 0.0f)) * (i1 * xv.y);
                pr[rloc * BN + nl]     = make_float2(at0, bt0);
                pr[rloc * BN + nl + 1] = make_float2(at1, bt1);
            }
        }
    }
    __syncthreads();

    // --- Chunk-pair reduction: 4 segments of 32 rows per channel ---
    {
        const int ch  = tid & 63;
        const int seg = tid >> 6;
        float A = 1.0f, Bv = 0.0f;
        #pragma unroll 8
        for (int r = 0; r < 32; r++) {
            const float2 v = pr[(seg * 32 + r) * BN + ch];
            Bv = fmaf(v.x, Bv, v.y);
            A *= v.x;
        }
        part[seg * 64 + ch] = make_float2(A, Bv);
    }
    __syncthreads();

    // --- Decoupled lookback across chunks (per n-tile, per batch) ---
    const int c  = (m0g >> 7) & 31;                 // chunk within batch
    const int fi = blockIdx.y * NTILES + blockIdx.x;
    volatile int* vflag = g_flag;

    float2 P;
    if (tid < 64) {
        P = part[tid];
        #pragma unroll
        for (int s = 1; s < 4; s++) {
            const float2 q = part[s * 64 + tid];
            P.y = fmaf(q.x, P.y, q.y);
            P.x *= q.x;
        }
        if (c > 0) g_agg[fi * 64 + tid] = P;        // publish aggregate payload
    }
    __syncthreads();
    if (tid == 0 && c > 0) {
        __threadfence();
        vflag[fi] = 1;
    }

    if (tid < 64) {
        float hin = 0.0f;
        if (c > 0) {
            float rA = 1.0f, rB = 0.0f;             // pending suffix combine
            int p = fi - NTILES;                    // predecessor chunk, same nt
            while (true) {
                int f;
                while ((f = vflag[p]) == 0) { __nanosleep(40); }
                __threadfence();
                if (f == 2) {
                    const float hprev = g_incl[p * 64 + tid];
                    hin = fmaf(rA, hprev, rB);
                    break;
                } else {
                    const float2 q = g_agg[p * 64 + tid];
                    rB = fmaf(rA, q.y, rB);
                    rA *= q.x;
                    p -= NTILES;
                }
            }
        }
        g_incl[fi * 64 + tid] = fmaf(P.x, hin, P.y);   // inclusive h at chunk end
        hin_s[tid] = hin;
    }
    __syncthreads();
    if (tid == 0) {
        __threadfence();
        vflag[fi] = 2;
    }

    // --- Serial scan of 32 rows per (segment, channel); direct y write ---
    {
        const int ch  = tid & 63;
        const int seg = tid >> 6;
        float h = hin_s[ch];
        #pragma unroll
        for (int s = 0; s < 4; s++)
            if (s < seg) {
                const float2 q = part[s * 64 + ch];
                h = fmaf(q.x, h, q.y);
            }
        float* yr = y + (size_t)(m0g + seg * 32) * N_TOT + n0g + ch;
        #pragma unroll 8
        for (int r = 0; r < 32; r++) {
            const float2 v = pr[(seg * 32 + r) * BN + ch];
            h = fmaf(v.x, h, v.y);
            yr[(size_t)r * N_TOT] = h;
        }
    }
}

// ---------------------------------------------------------------------------
// Launch: inputs x, Wa, Wx, ba, bx, Lam. Output f32 [B,T,H].
// ---------------------------------------------------------------------------
extern "C" void kernel_launch(void* const* d_in, const int* in_sizes, int n_in,
                              void* d_out, int out_size)
{
    const float* x   = (const float*)d_in[0];
    const float* Wa  = (const float*)d_in[1];
    const float* Wx  = (const float*)d_in[2];
    const float* ba  = (const float*)d_in[3];
    const float* bx  = (const float*)d_in[4];
    const float* Lam = (const float*)d_in[5];
    float* y = (float*)d_out;

    cudaFuncSetAttribute(gemm_h, cudaFuncAttributeMaxDynamicSharedMemorySize, SMEM_DYN);

    pack_x_h<<<M_TOT * K_TOT / 2048, 256>>>(x);
    pack_w_h<<<2048, 256>>>(Wa, Wx);
    gemm_h<<<dim3(N_TOT / BN, M_TOT / BM), 256, SMEM_DYN>>>(x, ba, bx, Lam, y);
}

// round 15
// speedup vs baseline: 1.4328x; 1.0652x over previous
#include <cuda_runtime.h>
#include <cuda_fp16.h>
#include <math.h>
#include <stdint.h>

// Problem dims (fixed): B=8, T=4096, D=H=1024
#define M_TOT   32768
#define N_TOT   1024
#define K_TOT   1024
#define T_LEN   4096
#define NCH     8192
#define NCHUNK  32
#define CHUNK   128           // == BM

// GEMM tiling (round-11/14 proven config)
#define BM      128
#define BN      64            // h-channels per CTA (x2 weight matrices)
#define BK      32
#define NKT     (K_TOT / BK)  // 32
#define AS      40            // smem row stride in halves (conflict-free)
#define A_HALFS (BM * AS)             // 5120
#define B_HALFS (2 * BN * AS)         // 5120
#define STAGE_H (A_HALFS + B_HALFS)   // 10240 halves = 20480 B
#define STAGES  4
#define SMEM_DYN (STAGES * STAGE_H * 2)   // 81920 B (>= 64KB pr + 2KB part + hin)

#define NTILES  16                         // n-tiles
#define NFLAGS  (256 * NTILES)             // (b,c) x nt = 4096

#define XPACK_BLOCKS (M_TOT * K_TOT / 2048)   // 16384
#define WPACK_BLOCKS 2048

// Scratch (static device memory — no dynamic allocation allowed)
__device__ __half g_xh[(size_t)M_TOT * K_TOT];   // fp16 x, [m][k]
__device__ __half g_wh[2 * N_TOT * K_TOT];       // fp16 Wa||Wx transposed, [w][n][k]
__device__ float2 g_agg[NFLAGS * BN];            // per-(tile) chunk aggregate pairs
__device__ float  g_incl[NFLAGS * BN];           // per-(tile) inclusive h at chunk end
__device__ int    g_flag[NFLAGS];                // 0=none, 1=aggregate, 2=inclusive

// ---------------------------------------------------------------------------
// helpers
// ---------------------------------------------------------------------------
__device__ __forceinline__ uint32_t s2u(const void* p) {
    uint32_t a;
    asm("{ .reg .u64 t; cvta.to.shared.u64 t, %1; cvt.u32.u64 %0, t; }"
        : "=r"(a) : "l"(p));
    return a;
}
__device__ __forceinline__ void cp16(uint32_t dst, const void* src) {
    // .cg: bypass L1 allocation (L2 -> smem); keeps the L1 pipe free for LDSM
    asm volatile("cp.async.cg.shared.global [%0], [%1], 16;" :: "r"(dst), "l"(src) : "memory");
}
__device__ __forceinline__ void cp_commit() {
    asm volatile("cp.async.commit_group;" ::: "memory");
}
__device__ __forceinline__ void cp_wait2() {
    asm volatile("cp.async.wait_group 2;" ::: "memory");
}
__device__ __forceinline__ void cp_wait0() {
    asm volatile("cp.async.wait_group 0;" ::: "memory");
}
#define LDSM4(r0, r1, r2, r3, addr) \
    asm volatile("ldmatrix.sync.aligned.m8n8.x4.shared.b16 {%0,%1,%2,%3}, [%4];" \
        : "=r"(r0), "=r"(r1), "=r"(r2), "=r"(r3) : "r"(addr))
__device__ __forceinline__ void mma_h(float* c, const uint32_t* a, const uint32_t* b) {
    asm volatile("mma.sync.aligned.m16n8k16.row.col.f32.f16.f16.f32 "
        "{%0,%1,%2,%3}, {%4,%5,%6,%7}, {%8,%9}, {%0,%1,%2,%3};"
        : "+f"(c[0]), "+f"(c[1]), "+f"(c[2]), "+f"(c[3])
        : "r"(a[0]), "r"(a[1]), "r"(a[2]), "r"(a[3]), "r"(b[0]), "r"(b[1]));
}
__device__ __forceinline__ float sigm(float v) {
    return __fdividef(1.0f, 1.0f + __expf(-v));
}

// ---------------------------------------------------------------------------
// Combined pack kernel:
//   blocks [0, XPACK_BLOCKS)                    : x -> fp16 [m][k]
//   blocks [XPACK_BLOCKS, XPACK_BLOCKS+WPACK)   : W -> fp16 transposed [w][n][k]
//   blocks [0, NFLAGS/256)                      : also clear lookback flags
// ---------------------------------------------------------------------------
__global__ void pack_all(const float* __restrict__ x,
                         const float* __restrict__ Wa,
                         const float* __restrict__ Wx)
{
    __shared__ float tile[32][33];
    const int tid = threadIdx.x;

    if (blockIdx.x < XPACK_BLOCKS) {
        if (blockIdx.x < NFLAGS / 256)
            g_flag[blockIdx.x * 256 + tid] = 0;
        const size_t i = ((size_t)blockIdx.x * 256 + tid) * 8;
        const float4 v0 = *(const float4*)(x + i);
        const float4 v1 = *(const float4*)(x + i + 4);
        __half2 h[4];
        h[0] = __floats2half2_rn(v0.x, v0.y);
        h[1] = __floats2half2_rn(v0.z, v0.w);
        h[2] = __floats2half2_rn(v1.x, v1.y);
        h[3] = __floats2half2_rn(v1.z, v1.w);
        *(uint4*)(g_xh + i) = *(uint4*)h;
    } else {
        const int bi = blockIdx.x - XPACK_BLOCKS;   // 0..2047
        const int w  = bi >> 10;
        const int kb = (bi >> 5) & 31;
        const int nb = bi & 31;
        const float* W = w ? Wx : Wa;
        const int k0 = kb * 32, n0 = nb * 32;
        #pragma unroll
        for (int p = 0; p < 4; p++) {
            const int kk = (tid >> 5) + p * 8;
            const int n  = tid & 31;
            tile[kk][n] = W[(size_t)(k0 + kk) * N_TOT + n0 + n];
        }
        __syncthreads();
        #pragma unroll
        for (int p = 0; p < 4; p++) {
            const int n = (tid >> 5) + p * 8;
            const int k = tid & 31;
            g_wh[((size_t)w * N_TOT + n0 + n) * K_TOT + k0 + k] = __float2half_rn(tile[k][n]);
        }
    }
}

// ---------------------------------------------------------------------------
// fp16 mma.sync dual-GEMM (ldmatrix + 4-stage pipe, f32 accum) + fused gates
// + single-pass decoupled-lookback scan + direct y write.
// grid (16 n-tiles, 256 m-tiles), 256 threads (8 warps: 4M x 2N)
// ---------------------------------------------------------------------------
__global__ __launch_bounds__(256, 2)
void gemm_h(const float* __restrict__ x, const float* __restrict__ ba,
            const float* __restrict__ bx, const float* __restrict__ Lam,
            float* __restrict__ y)
{
    extern __shared__ __half smh[];
    __shared__ float a_s[BN], ba_s[BN], bx_s[BN];

    const int tid  = threadIdx.x;
    const int wid  = tid >> 5, lane = tid & 31;
    const int gid  = lane >> 2, tq = lane & 3;
    const int wm   = wid & 3, wn = wid >> 2;
    const int n0g  = blockIdx.x * BN;
    const int m0g  = blockIdx.y * BM;

    if (tid < BN) {
        const int n = n0g + tid;
        a_s[tid]  = sigm(Lam[n]);
        ba_s[tid] = ba[n];
        bx_s[tid] = bx[n];
    }

    // cp.async mapping: 128 rows x 4 slots of 8 halves, for A and for B
    const int ar = tid >> 2;     // 0..63
    const int ac = tid & 3;      // slot 0..3
    const uint32_t smb = s2u(smh);

    auto issue_stage = [&](int kt, int s) {
        const int k0 = kt * BK;
        const uint32_t st = smb + s * STAGE_H * 2;
        #pragma unroll
        for (int r = 0; r < 2; r++) {
            const int row = ar + r * 64;                   // 0..127
            cp16(st + (row * AS + ac * 8) * 2,
                 g_xh + (size_t)(m0g + row) * K_TOT + k0 + ac * 8);
        }
        #pragma unroll
        for (int r = 0; r < 2; r++) {
            const int row = ar + r * 64;                   // 0..127: w=row>>6, n=row&63
            const int w = row >> 6, n = row & 63;
            cp16(st + (A_HALFS + row * AS + ac * 8) * 2,
                 g_wh + ((size_t)w * N_TOT + n0g + n) * K_TOT + k0 + ac * 8);
        }
    };

    const int m_base = wm * 32;
    const int n_base = wn * 32;

    // ldmatrix per-thread byte offsets (within a stage)
    uint32_t a_off[2];
    #pragma unroll
    for (int mi = 0; mi < 2; mi++)
        a_off[mi] = ((m_base + mi * 16 + (lane & 15)) * AS + (lane >> 4) * 8) * 2;
    uint32_t b_off[2][2];   // [set: 0=Wa,1=Wx][p]
    #pragma unroll
    for (int set = 0; set < 2; set++)
        #pragma unroll
        for (int p = 0; p < 2; p++)
            b_off[set][p] = (A_HALFS +
                (set * 64 + n_base + p * 16 + (lane & 7) + ((lane >> 4) & 1) * 8) * AS +
                ((lane >> 3) & 1) * 8) * 2;

    float accA[2][4][4], accX[2][4][4];
    #pragma unroll
    for (int mi = 0; mi < 2; mi++)
        #pragma unroll
        for (int ni = 0; ni < 4; ni++)
            #pragma unroll
            for (int j = 0; j < 4; j++) { accA[mi][ni][j] = 0.f; accX[mi][ni][j] = 0.f; }

    issue_stage(0, 0); cp_commit();
    issue_stage(1, 1); cp_commit();
    issue_stage(2, 2); cp_commit();

    for (int kt = 0; kt < NKT; kt++) {
        cp_wait2();
        __syncthreads();
        const uint32_t stb = smb + (kt & 3) * STAGE_H * 2;

        #pragma unroll
        for (int s = 0; s < 2; s++) {
            const uint32_t ksb = stb + s * 32;
            uint32_t af[2][4];
            #pragma unroll
            for (int mi = 0; mi < 2; mi++)
                LDSM4(af[mi][0], af[mi][1], af[mi][2], af[mi][3], ksb + a_off[mi]);
            uint32_t bfa[4][2], bfx[4][2];
            #pragma unroll
            for (int p = 0; p < 2; p++) {
                LDSM4(bfa[2*p][0], bfa[2*p][1], bfa[2*p+1][0], bfa[2*p+1][1], ksb + b_off[0][p]);
                LDSM4(bfx[2*p][0], bfx[2*p][1], bfx[2*p+1][0], bfx[2*p+1][1], ksb + b_off[1][p]);
            }
            #pragma unroll
            for (int mi = 0; mi < 2; mi++)
                #pragma unroll
                for (int ni = 0; ni < 4; ni++) {
                    mma_h(accA[mi][ni], af[mi], bfa[ni]);
                    mma_h(accX[mi][ni], af[mi], bfx[ni]);
                }
        }
        // Prefetch AFTER the MMA block (measured optimum): slot (kt+3)&3 ==
        // (kt-1)&3; all warps finished reading it pre-barrier.
        if (kt + 3 < NKT) issue_stage(kt + 3, (kt + 3) & 3);
        cp_commit();
    }

    // --- Epilogue: gate math -> smem (at,bt) staging ---
    cp_wait0();
    __syncthreads();                       // pipeline smem now dead; reuse below
    float2* pr   = (float2*)smh;                 // [128 rows][64 ch], 64 KB
    float2* part = (float2*)(smh + 65536 / 2);   // [4 seg][64 ch], 2 KB
    float*  hin_s = (float*)(part + 256);        // [64 ch], 256 B

    #pragma unroll
    for (int mi = 0; mi < 2; mi++) {
        #pragma unroll
        for (int half = 0; half < 2; half++) {
            const int rloc = m_base + mi * 16 + gid + half * 8;     // 0..127
            const int row  = m0g + rloc;
            const float* xr = x + (size_t)row * N_TOT;
            #pragma unroll
            for (int ni = 0; ni < 4; ni++) {
                const int nl = n_base + ni * 8 + tq * 2;
                const int n  = n0g + nl;
                const float vA0 = accA[mi][ni][half * 2];
                const float vA1 = accA[mi][ni][half * 2 + 1];
                const float vX0 = accX[mi][ni][half * 2];
                const float vX1 = accX[mi][ni][half * 2 + 1];
                const float2 xv = *(const float2*)(xr + n);
                const float r0 = sigm(vA0 + ba_s[nl]);
                const float r1 = sigm(vA1 + ba_s[nl + 1]);
                const float i0 = sigm(vX0 + bx_s[nl]);
                const float i1 = sigm(vX1 + bx_s[nl + 1]);
                const float at0 = a_s[nl]     * exp2f(-3.0f * r0);
                const float at1 = a_s[nl + 1] * exp2f(-3.0f * r1);
                const float bt0 = sqrtf(fmaxf(1.0f - at0 * at0, 0.0f)) * (i0 * xv.x);
                const float bt1 = sqrtf(fmaxf(1.0f - at1 * at1, 0.0f)) * (i1 * xv.y);
                pr[rloc * BN + nl]     = make_float2(at0, bt0);
                pr[rloc * BN + nl + 1] = make_float2(at1, bt1);
            }
        }
    }
    __syncthreads();

    // --- Chunk-pair reduction: 4 segments of 32 rows per channel ---
    {
        const int ch  = tid & 63;
        const int seg = tid >> 6;
        float A = 1.0f, Bv = 0.0f;
        #pragma unroll 8
        for (int r = 0; r < 32; r++) {
            const float2 v = pr[(seg * 32 + r) * BN + ch];
            Bv = fmaf(v.x, Bv, v.y);
            A *= v.x;
        }
        part[seg * 64 + ch] = make_float2(A, Bv);
    }
    __syncthreads();

    // --- Decoupled lookback across chunks (per n-tile, per batch) ---
    const int c  = (m0g >> 7) & 31;                 // chunk within batch
    const int fi = blockIdx.y * NTILES + blockIdx.x;
    volatile int* vflag = g_flag;

    float2 P;
    if (tid < 64) {
        P = part[tid];
        #pragma unroll
        for (int s = 1; s < 4; s++) {
            const float2 q = part[s * 64 + tid];
            P.y = fmaf(q.x, P.y, q.y);
            P.x *= q.x;
        }
        if (c > 0) g_agg[fi * 64 + tid] = P;        // publish aggregate payload
    }
    __syncthreads();
    if (tid == 0 && c > 0) {
        __threadfence();
        vflag[fi] = 1;
    }

    if (tid < 64) {
        float hin = 0.0f;
        if (c > 0) {
            float rA = 1.0f, rB = 0.0f;             // pending suffix combine
            int p = fi - NTILES;                    // predecessor chunk, same nt
            while (true) {
                int f;
                while ((f = vflag[p]) == 0) { __nanosleep(40); }
                __threadfence();
                if (f == 2) {
                    const float hprev = g_incl[p * 64 + tid];
                    hin = fmaf(rA, hprev, rB);
                    break;
                } else {
                    const float2 q = g_agg[p * 64 + tid];
                    rB = fmaf(rA, q.y, rB);
                    rA *= q.x;
                    p -= NTILES;
                }
            }
        }
        g_incl[fi * 64 + tid] = fmaf(P.x, hin, P.y);   // inclusive h at chunk end
        hin_s[tid] = hin;
    }
    __syncthreads();
    if (tid == 0) {
        __threadfence();
        vflag[fi] = 2;
    }

    // --- Serial scan of 32 rows per (segment, channel); direct y write ---
    {
        const int ch  = tid & 63;
        const int seg = tid >> 6;
        float h = hin_s[ch];
        #pragma unroll
        for (int s = 0; s < 4; s++)
            if (s < seg) {
                const float2 q = part[s * 64 + ch];
                h = fmaf(q.x, h, q.y);
            }
        float* yr = y + (size_t)(m0g + seg * 32) * N_TOT + n0g + ch;
        #pragma unroll 8
        for (int r = 0; r < 32; r++) {
            const float2 v = pr[(seg * 32 + r) * BN + ch];
            h = fmaf(v.x, h, v.y);
            yr[(size_t)r * N_TOT] = h;
        }
    }
}

// ---------------------------------------------------------------------------
// Launch: inputs x, Wa, Wx, ba, bx, Lam. Output f32 [B,T,H].
// ---------------------------------------------------------------------------
extern "C" void kernel_launch(void* const* d_in, const int* in_sizes, int n_in,
                              void* d_out, int out_size)
{
    const float* x   = (const float*)d_in[0];
    const float* Wa  = (const float*)d_in[1];
    const float* Wx  = (const float*)d_in[2];
    const float* ba  = (const float*)d_in[3];
    const float* bx  = (const float*)d_in[4];
    const float* Lam = (const float*)d_in[5];
    float* y = (float*)d_out;

    cudaFuncSetAttribute(gemm_h, cudaFuncAttributeMaxDynamicSharedMemorySize, SMEM_DYN);

    pack_all<<<XPACK_BLOCKS + WPACK_BLOCKS, 256>>>(x, Wa, Wx);
    gemm_h<<<dim3(N_TOT / BN, M_TOT / BM), 256, SMEM_DYN>>>(x, ba, bx, Lam, y);
}